// round 11
// baseline (speedup 1.0000x reference)
#include <cuda_runtime.h>
#include <math.h>

#define BB 128
#define TT 48
#define DD 512
#define MM 64
#define NC 2000

typedef unsigned long long u64;

// ---------------- f32x2 packed helpers (sm_100+) -----------------------------
__device__ __forceinline__ u64 ffma2(u64 a, u64 b, u64 c){
  u64 d; asm("fma.rn.f32x2 %0, %1, %2, %3;" : "=l"(d) : "l"(a), "l"(b), "l"(c));
  return d;
}
__device__ __forceinline__ u64 f2pack(float lo, float hi){
  u64 r; asm("mov.b64 %0, {%1, %2};" : "=l"(r) : "f"(lo), "f"(hi)); return r;
}
__device__ __forceinline__ void f2unp(u64 v, float& lo, float& hi){
  asm("mov.b64 {%0, %1}, %2;" : "=f"(lo), "=f"(hi) : "l"(v));
}
__device__ __forceinline__ float f2sum(u64 v){
  float lo, hi; f2unp(v, lo, hi); return lo + hi;
}

// ---------------- static device scratch --------------------------------------
struct Scratch {
  float w_table[NC*MM];
  unsigned long long sig_table[NC*2];
  float kproj_t[2048*DD];
  float eaproj_t[4096*2*DD];
  float Aea[2*DD*DD];
  float Bea[2*DD*DD];
  float Sw[2*DD*DD];
  float WaT[DD*DD];
  float Wa2T[DD*DD];
  float bias_ea[2*DD];
  float rd[BB*DD];
  float f[TT*BB*DD];
  float ea[BB*2*DD];
  float xproj[TT*BB*4*DD];
  float H[(TT+1)*BB*DD];
  float C[(TT+1)*BB*DD];
  float bihh[4*DD];
  int src[TT*BB];
  int qidx[TT*BB];                // layout t*BB + b
  int xidx[TT*BB];
};
__device__ Scratch gS;

// barrier counters: memrec 3 replicas x 8 groups x 144 slots, lstm 4 x 48
#define MSLOTS 144
#define MREP 3
__device__ unsigned gBarM[MREP*8*MSLOTS];
__device__ unsigned gBarL[4*TT];

__device__ __forceinline__ float sigm(float x){ return 1.f/(1.f+expf(-x)); }

// Group barrier: acq_rel atomic arrival + ld.acquire spin (round-7 protocol,
// formally correct per PTX memory model: acquire orders subsequent data loads).
__device__ __forceinline__ void gbar_g(unsigned* ctr, int slot, unsigned nb){
  __syncthreads();
  if (threadIdx.x == 0){
    unsigned prev;
    asm volatile("atom.add.acq_rel.gpu.u32 %0, [%1], 1;"
                 : "=r"(prev) : "l"(ctr + slot) : "memory");
    if (prev + 1u < nb){
      unsigned v = 0, it = 0;
      do {
        asm volatile("ld.acquire.gpu.u32 %0, [%1];"
                     : "=r"(v) : "l"(ctr + slot) : "memory");
      } while (v < nb && ++it < 2000000u);
    }
  }
  __syncthreads();
}

// ---------------- combo setup kernel ----------------------------------------
#define EW_HC    (BB*DD)            // 65536
#define EW_IDX   (TT*BB)            // 6144
#define EW_BIHH  (4*DD)             // 2048
#define EW_TRANS (DD*DD)            // 262144
#define EW_STACK (DD*DD)            // 262144
#define EW_BARS  (MREP*8*MSLOTS + 4*TT)
#define EW_TOTAL (EW_HC+EW_IDX+EW_BIHH+EW_TRANS+EW_STACK+EW_BARS)
#define NB_A ((EW_TOTAL + 255)/256)

__global__ __launch_bounds__(256) void combo_kernel(
    const int* __restrict__ q, const int* __restrict__ r,
    const float* __restrict__ hx0, const float* __restrict__ cx0,
    const float* __restrict__ bih, const float* __restrict__ bhh,
    const float* __restrict__ Wa,
    const float* __restrict__ We, const float* __restrict__ Wadd,
    const float* __restrict__ ba, const float* __restrict__ be,
    const float* __restrict__ badd,
    const float* __restrict__ Mk, const float* __restrict__ k_table)
{
  int blk = blockIdx.x;
  int tid = threadIdx.x;
  if (blk < NB_A){
    int i = blk*256 + tid;
    if (i < EW_HC){
      gS.H[i] = hx0[i % DD]; gS.C[i] = cx0[i % DD];
    } else if ((i -= EW_HC) < EW_IDX){
      int t = i / BB, b = i % BB;
      int qi = q[b*TT + t];
      int ri = r[b*TT + t];
      gS.qidx[i] = qi;
      gS.xidx[i] = qi + NC*ri;
    } else if ((i -= EW_IDX) < EW_BIHH){
      gS.bihh[i] = bih[i] + bhh[i];
    } else if ((i -= EW_BIHH) < EW_TRANS){
      int j = i / DD, k = i % DD;
      gS.WaT[i]  = Wa[(long)k*(2*DD) + j];
      gS.Wa2T[i] = Wa[(long)k*(2*DD) + DD + j];
    } else if ((i -= EW_TRANS) < EW_STACK){
      gS.Sw[i] = We[i]; gS.Sw[DD*DD + i] = Wadd[i];
    } else if ((i -= EW_STACK) < EW_BARS){
      if (i < MREP*8*MSLOTS) gBarM[i] = 0u; else gBarL[i - MREP*8*MSLOTS] = 0u;
    }
    return;
  }
  blk -= NB_A;
  if (blk < 128){
    int n = blk*8 + (tid >> 5);
    int lane = tid & 31;
    const float* row = (n < DD) ? (We + (long)n*DD) : (Wadd + (long)(n-DD)*DD);
    float s = 0.f;
    for (int k = lane; k < DD; k += 32) s += row[k]*ba[k];
    #pragma unroll
    for (int o = 16; o > 0; o >>= 1) s += __shfl_down_sync(0xffffffffu, s, o);
    if (lane == 0) gS.bias_ea[n] = s + ((n < DD) ? be[n] : badd[n-DD]);
    return;
  }
  blk -= 128;
  // ---- addressing softmax + signature for q id = blk ----
  {
    int id = blk;
    __shared__ float kv[DD];
    __shared__ float lg[MM];
    __shared__ float eg[MM];
    __shared__ unsigned char ivb[MM];
    const float* kr = k_table + (long)id*DD;
    kv[tid] = kr[tid]; kv[tid+256] = kr[tid+256];
    __syncthreads();
    int m = tid >> 2, part = tid & 3;
    const ulonglong2* mk2 = (const ulonglong2*)(Mk + (long)m*DD + part*128);
    const ulonglong2* kv2 = (const ulonglong2*)(kv + part*128);
    u64 acc2 = 0;
    #pragma unroll 8
    for (int k4 = 0; k4 < 32; k4++){
      ulonglong2 m2 = mk2[k4], k2 = kv2[k4];
      acc2 = ffma2(m2.x, k2.x, acc2);
      acc2 = ffma2(m2.y, k2.y, acc2);
    }
    float s = f2sum(acc2);
    s += __shfl_down_sync(0xffffffffu, s, 2, 4);
    s += __shfl_down_sync(0xffffffffu, s, 1, 4);
    if (part == 0) lg[m] = s;
    __syncthreads();
    if (tid < MM){
      float sv = lg[tid];
      float mx = -1e30f;
      for (int mm = 0; mm < MM; mm++) mx = fmaxf(mx, lg[mm]);
      eg[tid] = expf(sv - mx);
    }
    __syncthreads();
    if (tid < MM){
      float sum = 0.f;
      for (int mm = 0; mm < MM; mm++) sum += eg[mm];
      float wv = eg[tid] / sum;
      gS.w_table[(long)id*MM + tid] = wv;
      float mval = fminf((wv - 0.075f)/(0.088f - 0.075f), (1.0f - wv)/(1.0f - 0.088f));
      mval = fmaxf(mval, 0.f);
      int iv = (mval >= 0.6f) ? 2 : ((mval >= 0.1f) ? 1 : 0);
      ivb[tid] = (unsigned char)iv;
    }
    __syncthreads();
    if (tid < 2){
      unsigned long long sg = 0ull;
      #pragma unroll
      for (int i2 = 0; i2 < 32; i2++) sg |= ((unsigned long long)ivb[tid*32 + i2]) << (2*i2);
      gS.sig_table[(long)id*2 + tid] = sg;
    }
  }
}

__global__ void src_kernel(){
  int b = blockIdx.x;
  int tid = threadIdx.x;  // 64 threads
  __shared__ unsigned long long s0[TT], s1[TT];
  if (tid < TT){
    int id = gS.qidx[tid*BB + b];
    s0[tid] = gS.sig_table[(long)id*2];
    s1[tid] = gS.sig_table[(long)id*2 + 1];
  }
  __syncthreads();
  if (tid < TT){
    int i = tid, sr = i - 1;
    unsigned long long a0 = s0[i], a1 = s1[i];
    for (int j = i - 1; j >= 0; j--){
      if (s0[j] == a0 && s1[j] == a1){ sr = j; break; }
    }
    gS.src[i*BB + b] = sr;
  }
}

// ---------------- double-buffered 128x128x8 SGEMM body ----------------------
template<bool HB>
__device__ __forceinline__ void sgemm_body(
    const float* __restrict__ A, int Mrows,
    const float* __restrict__ W, int ldw,
    const float* __restrict__ bias,
    float* __restrict__ C, int ldc,
    int m0, int n0)
{
  __shared__ u64 As2[2][8][128];
  __shared__ float Bs[2][8][128];
  int tid = threadIdx.x;
  int tx = tid & 15, ty = tid >> 4;
  int lr = tid >> 1;
  int lk = (tid & 1) * 4;
  int mrow = m0 + lr;
  int mload = mrow < Mrows ? mrow : (Mrows - 1);
  const float4* Ap = (const float4*)(A + (long)mload*DD + lk);
  const float4* Wp = (const float4*)(W + (long)(n0 + lr)*ldw + lk);

  u64 acc2[8][4];
  #pragma unroll
  for (int i = 0; i < 8; i++)
    #pragma unroll
    for (int j = 0; j < 4; j++) acc2[i][j] = 0ull;

  float4 av = Ap[0];
  float4 bv = Wp[0];
  As2[0][lk+0][lr] = f2pack(av.x, av.x);
  As2[0][lk+1][lr] = f2pack(av.y, av.y);
  As2[0][lk+2][lr] = f2pack(av.z, av.z);
  As2[0][lk+3][lr] = f2pack(av.w, av.w);
  Bs[0][lk+0][lr] = bv.x; Bs[0][lk+1][lr] = bv.y;
  Bs[0][lk+2][lr] = bv.z; Bs[0][lk+3][lr] = bv.w;
  __syncthreads();

  for (int kb = 0; kb < 64; kb++){
    int cur = kb & 1, nxt = cur ^ 1;
    if (kb < 63){
      av = Ap[(kb+1)*2];
      bv = Wp[(kb+1)*2];
    }
    #pragma unroll
    for (int k = 0; k < 8; k++){
      const ulonglong2* a4 = (const ulonglong2*)&As2[cur][k][ty*8];
      ulonglong2 t0 = a4[0], t1 = a4[1], t2 = a4[2], t3 = a4[3];
      u64 a2[8] = {t0.x, t0.y, t1.x, t1.y, t2.x, t2.y, t3.x, t3.y};
      float4 bl = *(const float4*)&Bs[cur][k][tx*8];
      float4 bh = *(const float4*)&Bs[cur][k][tx*8+4];
      u64 b2[4] = {f2pack(bl.x, bl.y), f2pack(bl.z, bl.w),
                   f2pack(bh.x, bh.y), f2pack(bh.z, bh.w)};
      #pragma unroll
      for (int i = 0; i < 8; i++)
        #pragma unroll
        for (int j = 0; j < 4; j++) acc2[i][j] = ffma2(a2[i], b2[j], acc2[i][j]);
    }
    if (kb < 63){
      As2[nxt][lk+0][lr] = f2pack(av.x, av.x);
      As2[nxt][lk+1][lr] = f2pack(av.y, av.y);
      As2[nxt][lk+2][lr] = f2pack(av.z, av.z);
      As2[nxt][lk+3][lr] = f2pack(av.w, av.w);
      Bs[nxt][lk+0][lr] = bv.x; Bs[nxt][lk+1][lr] = bv.y;
      Bs[nxt][lk+2][lr] = bv.z; Bs[nxt][lk+3][lr] = bv.w;
    }
    __syncthreads();
  }
  #pragma unroll
  for (int i = 0; i < 8; i++){
    int m = m0 + ty*8 + i;
    if (m < Mrows){
      int n = n0 + tx*8;
      float c0,c1,c2,c3,c4,c5,c6,c7;
      f2unp(acc2[i][0], c0, c1); f2unp(acc2[i][1], c2, c3);
      f2unp(acc2[i][2], c4, c5); f2unp(acc2[i][3], c6, c7);
      float4 o0, o1;
      o0.x = c0 + (HB ? bias[n+0] : 0.f);
      o0.y = c1 + (HB ? bias[n+1] : 0.f);
      o0.z = c2 + (HB ? bias[n+2] : 0.f);
      o0.w = c3 + (HB ? bias[n+3] : 0.f);
      o1.x = c4 + (HB ? bias[n+4] : 0.f);
      o1.y = c5 + (HB ? bias[n+5] : 0.f);
      o1.z = c6 + (HB ? bias[n+6] : 0.f);
      o1.w = c7 + (HB ? bias[n+7] : 0.f);
      *(float4*)(C + (long)m*ldc + n)     = o0;
      *(float4*)(C + (long)m*ldc + n + 4) = o1;
    }
  }
}

template<bool HB>
__global__ __launch_bounds__(256,2) void sgemm2_k(
    const float* __restrict__ A, int Mrows,
    const float* __restrict__ W, int ldw,
    const float* __restrict__ bias,
    float* __restrict__ C, int ldc)
{
  sgemm_body<HB>(A, Mrows, W, ldw, bias, C, ldc, blockIdx.x*128, blockIdx.y*128);
}

// Dual GEMM: blockIdx.y < 4 -> Aea = Sw @ WaT^T ; else -> Bea = Sw @ Wa2T^T
__global__ __launch_bounds__(256,2) void sgemm2_dual_k(
    const float* __restrict__ Sw,
    const float* __restrict__ W0, const float* __restrict__ W1,
    float* __restrict__ C0, float* __restrict__ C1)
{
  int by = blockIdx.y;
  if (by < 4)
    sgemm_body<false>(Sw, 1024, W0, DD, nullptr, C0, DD, blockIdx.x*128, by*128);
  else
    sgemm_body<false>(Sw, 1024, W1, DD, nullptr, C1, DD, blockIdx.x*128, (by-4)*128);
}

// Fused projection GEMM: blocks [0,256) -> eaproj_t, [256,320) -> kproj_t.
__global__ __launch_bounds__(256,2) void proj_fused_k(
    const float* __restrict__ k_tab, const float* __restrict__ x_tab,
    const float* __restrict__ W_f, const float* __restrict__ b_f)
{
  int blk = blockIdx.x;
  if (blk < 256){
    sgemm_body<true>(x_tab, 2*NC+1, gS.Bea, DD, gS.bias_ea, gS.eaproj_t, 2*DD,
                     (blk & 31)*128, (blk >> 5)*128);
  } else {
    int i = blk - 256;
    sgemm_body<true>(k_tab, NC, W_f + DD, 2*DD, b_f, gS.kproj_t, DD,
                     (i & 15)*128, (i >> 4)*128);
  }
}

// ---------------- persistent memory recurrence ------------------------------
// IDEMPOTENT: re-initializes mem from Mv0 and recomputes rd/f/ea to identical
// values. Launched MREP times (diagnostic) with disjoint barrier-slot bases.
#define MEMREC_SMEM ((MM*DD + 16*516 + 128)*4)

__global__ __launch_bounds__(512) void memrec_kernel(
    const float* __restrict__ Mv0, const float* __restrict__ W_f, int slotbase)
{
  extern __shared__ float sm[];
  float* mem_s = sm;                 // 64*512
  float* tile  = sm + MM*DD;         // 16*516
  float* w0s   = tile + 16*516;      // 64
  float* w1s   = w0s + 64;           // 64
  int bid = blockIdx.x, tid = threadIdx.x;
  int bq = bid >> 4, cq = bid & 15;
  int b0 = bq * 16;
  int myb = bid;
  unsigned* ctr = gBarM + slotbase + bq*MSLOTS;

  {
    const float4* s4 = (const float4*)Mv0;
    float4* d4 = (float4*)mem_s;
    #pragma unroll 4
    for (int i = tid; i < MM*DD/4; i += 512) d4[i] = s4[i];
  }
  if (tid < MM){
    int qid = gS.qidx[myb];   // t = 0
    w0s[tid] = gS.w_table[(long)qid*MM + tid];
  }
  __syncthreads();
  {
    int d = tid;
    float acc = 0.f;
    #pragma unroll 8
    for (int m = 0; m < MM; m++) acc += w0s[m]*mem_s[m*DD + d];
    gS.rd[myb*DD + d] = acc;
  }
  int slot = 0;
  gbar_g(ctr, slot++, 16);

  for (int t = 0; t < TT; t++){
    // ---- stage1: f_t = tanh(Wf1 @ rd + kproj_table[q]) ----
    {
      for (int i = tid; i < 16*DD/4; i += 512){
        int rr = i >> 7, k4 = i & 127;
        *(float4*)(tile + rr*516 + k4*4) =
            __ldcg((const float4*)(gS.rd + (b0+rr)*DD) + k4);
      }
      __syncthreads();
      int bl = tid & 15, cl = tid >> 4;
      int c = cq*32 + cl;
      const ulonglong2* wr2 = (const ulonglong2*)(W_f + (long)c*(2*DD));
      const ulonglong2* rv2 = (const ulonglong2*)(tile + bl*516);
      u64 acc2 = 0;
      #pragma unroll 8
      for (int k4 = 0; k4 < 128; k4++){
        ulonglong2 wv = wr2[k4], rv = rv2[k4];
        acc2 = ffma2(wv.x, rv.x, acc2);
        acc2 = ffma2(wv.y, rv.y, acc2);
      }
      int brow = b0 + bl;
      int qid = gS.qidx[t*BB + brow];
      float acc = f2sum(acc2) + gS.kproj_t[(long)qid*DD + c];
      gS.f[((long)t*BB + brow)*DD + c] = tanhf(acc);
    }
    if (t == TT-1) break;
    gbar_g(ctr, slot++, 16);

    // ---- stage2: [e|a]_t = act(Aea @ f_t + eaproj_table[x]) ----
    {
      for (int i = tid; i < 16*DD/4; i += 512){
        int rr = i >> 7, k4 = i & 127;
        *(float4*)(tile + rr*516 + k4*4) =
            __ldcg((const float4*)(gS.f + ((long)t*BB + b0 + rr)*DD) + k4);
      }
      __syncthreads();
      int bl = tid & 15, cp = tid >> 4;
      int c0 = cq*64 + cp*2;
      const ulonglong2* a0 = (const ulonglong2*)(gS.Aea + (long)c0*DD);
      const ulonglong2* a1 = (const ulonglong2*)(gS.Aea + (long)(c0+1)*DD);
      const ulonglong2* fv2 = (const ulonglong2*)(tile + bl*516);
      u64 acc0_2 = 0, acc1_2 = 0;
      #pragma unroll 8
      for (int k4 = 0; k4 < 128; k4++){
        ulonglong2 fv = fv2[k4];
        ulonglong2 w0v = a0[k4], w1v = a1[k4];
        acc0_2 = ffma2(w0v.x, fv.x, acc0_2);
        acc0_2 = ffma2(w0v.y, fv.y, acc0_2);
        acc1_2 = ffma2(w1v.x, fv.x, acc1_2);
        acc1_2 = ffma2(w1v.y, fv.y, acc1_2);
      }
      int brow = b0 + bl;
      int xid = gS.xidx[t*BB + brow];
      const float* ep = gS.eaproj_t + (long)xid*(2*DD);
      float v0 = f2sum(acc0_2) + ep[c0];
      float v1 = f2sum(acc1_2) + ep[c0+1];
      float* eo = gS.ea + brow*(2*DD);
      if (cq < 8){ eo[c0] = sigm(v0); eo[c0+1] = sigm(v1); }
      else       { eo[c0] = tanhf(v0); eo[c0+1] = tanhf(v1); }
    }
    gbar_g(ctr, slot++, 16);

    // ---- stage3: mem update (SMEM-resident) + rd_{t+1} ----
    {
      if (tid < MM){
        int q0 = gS.qidx[t*BB + myb];
        int q1 = gS.qidx[(t+1)*BB + myb];
        w0s[tid] = gS.w_table[(long)q0*MM + tid];
        w1s[tid] = gS.w_table[(long)q1*MM + tid];
      }
      __syncthreads();
      int d = tid;
      float ev = __ldcg(&gS.ea[myb*(2*DD) + d]);
      float av = __ldcg(&gS.ea[myb*(2*DD) + DD + d]);
      float acc = 0.f;
      #pragma unroll 8
      for (int m = 0; m < MM; m++){
        float v = mem_s[m*DD + d];
        v = v*(1.f - w0s[m]*ev) + w0s[m]*av;
        mem_s[m*DD + d] = v;
        acc += w1s[m]*v;
      }
      gS.rd[myb*DD + d] = acc;
    }
    gbar_g(ctr, slot++, 16);
  }
}

// ---------------- persistent hop-LSTM (register-tiled, transposed H) --------
#define LSTM_SMEM ((64*516 + 512*32)*4)

__global__ __launch_bounds__(256) void lstm_kernel(const float* __restrict__ Whh){
  extern __shared__ float sm[];
  float* Ws  = sm;                 // 64 rows (o=(g<<4)|n) x 516
  float* HsT = sm + 64*516;        // [512 k][32 b]
  float* red = HsT;                // alias after k-loop: [4 ks][32 b][64 o]
  __shared__ int ssrc[32];
  int bid = blockIdx.x, tid = threadIdx.x;
  int n0 = (bid & 31) * 16;
  int b0 = (bid >> 5) * 32;
  unsigned* ctr = gBarL + (bid >> 5)*TT;

  {
    float4* WsV = (float4*)Ws;
    const float4* WhhV = (const float4*)Whh;
    for (int i = tid; i < 64*128; i += 256){
      int o = i >> 7, k4 = i & 127;
      int g = o >> 4, n = o & 15;
      WsV[o*129 + k4] = WhhV[(long)(g*DD + n0 + n)*128 + k4];
    }
  }
  __syncthreads();

  int og = tid & 7;
  int bg = (tid >> 3) & 7;
  int ks = tid >> 6;
  const ulonglong2* WsU = (const ulonglong2*)Ws;

  for (int t = 0; t < TT; t++){
    if (tid < 32) ssrc[tid] = gS.src[t*BB + b0 + tid];
    __syncthreads();
    for (int i = tid; i < 32*128; i += 256){
      int b = i & 31, k4 = i >> 5;
      long hrow = ((long)(ssrc[b]+1)*BB + (b0 + b))*DD;
      float4 hv = __ldcg((const float4*)(gS.H + hrow) + k4);
      int kb = k4*4;
      HsT[(kb+0)*32 + b] = hv.x;
      HsT[(kb+1)*32 + b] = hv.y;
      HsT[(kb+2)*32 + b] = hv.z;
      HsT[(kb+3)*32 + b] = hv.w;
    }
    __syncthreads();

    u64 acc[4][8];
    #pragma unroll
    for (int i2 = 0; i2 < 4; i2++)
      #pragma unroll
      for (int j = 0; j < 8; j++) acc[i2][j] = 0ull;

    int kb0 = ks*32;
    #pragma unroll 2
    for (int it = 0; it < 32; it++){
      int k4 = kb0 + it;
      int kw = k4*4;
      float4 h0 = *(const float4*)&HsT[(kw+0)*32 + bg*4];
      float4 h1 = *(const float4*)&HsT[(kw+1)*32 + bg*4];
      float4 h2 = *(const float4*)&HsT[(kw+2)*32 + bg*4];
      float4 h3 = *(const float4*)&HsT[(kw+3)*32 + bg*4];
      u64 p01[4], p23[4];
      p01[0] = f2pack(h0.x, h1.x); p01[1] = f2pack(h0.y, h1.y);
      p01[2] = f2pack(h0.z, h1.z); p01[3] = f2pack(h0.w, h1.w);
      p23[0] = f2pack(h2.x, h3.x); p23[1] = f2pack(h2.y, h3.y);
      p23[2] = f2pack(h2.z, h3.z); p23[3] = f2pack(h2.w, h3.w);
      #pragma unroll
      for (int j = 0; j < 8; j++){
        ulonglong2 wv = WsU[(long)(j*8 + og)*129 + k4];
        #pragma unroll
        for (int i2 = 0; i2 < 4; i2++){
          acc[i2][j] = ffma2(wv.x, p01[i2], acc[i2][j]);
          acc[i2][j] = ffma2(wv.y, p23[i2], acc[i2][j]);
        }
      }
    }
    __syncthreads();

    #pragma unroll
    for (int i2 = 0; i2 < 4; i2++){
      int b = bg*4 + i2;
      #pragma unroll
      for (int j = 0; j < 8; j++)
        red[((ks*32) + b)*64 + (j*8 + og)] = f2sum(acc[i2][j]);
    }
    __syncthreads();

    #pragma unroll
    for (int e = 0; e < 2; e++){
      int p = tid*2 + e;
      int b = p >> 4, n = p & 15;
      float g4[4];
      #pragma unroll
      for (int g = 0; g < 4; g++){
        int o = g*16 + n;
        g4[g] = red[(0*32 + b)*64 + o] + red[(1*32 + b)*64 + o]
              + red[(2*32 + b)*64 + o] + red[(3*32 + b)*64 + o];
      }
      const float* xp = gS.xproj + ((long)t*BB + b0 + b)*(4*DD);
      float gi = g4[0] + xp[n0 + n];
      float gf = g4[1] + xp[DD + n0 + n];
      float gg = g4[2] + xp[2*DD + n0 + n];
      float go = g4[3] + xp[3*DD + n0 + n];
      int srcp = ssrc[b] + 1;
      float cin = __ldcg(&gS.C[((long)srcp*BB + b0 + b)*DD + n0 + n]);
      float c = sigm(gf)*cin + sigm(gi)*tanhf(gg);
      float h = sigm(go)*tanhf(c);
      long o = ((long)(t+1)*BB + b0 + b)*DD + n0 + n;
      gS.H[o] = h;
      gS.C[o] = c;
    }
    if (t < TT-1) gbar_g(ctr, t, 32);
  }
}

// ---------------- prediction head -------------------------------------------
__global__ void head_kernel(const float* __restrict__ Wp, const float* __restrict__ bp,
                            float* __restrict__ out){
  int gw = (blockIdx.x*blockDim.x + threadIdx.x) >> 5;
  int lane = threadIdx.x & 31;
  if (gw >= BB*TT) return;
  int b = gw / TT, t = gw % TT;
  const float* h = gS.H + ((long)(t+1)*BB + b)*DD;
  float s = 0.f;
  for (int j = lane; j < DD; j += 32) s += h[j]*Wp[j];
  #pragma unroll
  for (int o = 16; o > 0; o >>= 1) s += __shfl_down_sync(0xffffffffu, s, o);
  if (lane == 0) out[b*TT + t] = sigm(s + bp[0]);
}

// ---------------- host orchestration ----------------------------------------
extern "C" void kernel_launch(void* const* d_in, const int* in_sizes, int n_in,
                              void* d_out, int out_size){
  (void)in_sizes; (void)n_in; (void)out_size;
  const int*   q     = (const int*)d_in[0];
  const int*   r     = (const int*)d_in[1];
  const float* Mk    = (const float*)d_in[2];
  const float* Mv0   = (const float*)d_in[3];
  const float* k_tab = (const float*)d_in[4];
  const float* x_tab = (const float*)d_in[5];
  const float* W_e   = (const float*)d_in[6];
  const float* b_e   = (const float*)d_in[7];
  const float* W_add = (const float*)d_in[8];
  const float* b_add = (const float*)d_in[9];
  const float* W_a   = (const float*)d_in[10];
  const float* b_a   = (const float*)d_in[11];
  const float* W_f   = (const float*)d_in[12];
  const float* b_f   = (const float*)d_in[13];
  const float* W_ih  = (const float*)d_in[14];
  const float* W_hh  = (const float*)d_in[15];
  const float* b_ih  = (const float*)d_in[16];
  const float* b_hh  = (const float*)d_in[17];
  const float* hx0   = (const float*)d_in[18];
  const float* cx0   = (const float*)d_in[19];
  const float* W_p   = (const float*)d_in[20];
  const float* b_p   = (const float*)d_in[21];
  float* out = (float*)d_out;

  Scratch* S = nullptr;
  cudaGetSymbolAddress((void**)&S, gS);

  cudaFuncSetAttribute(memrec_kernel, cudaFuncAttributeMaxDynamicSharedMemorySize, MEMREC_SMEM);
  cudaFuncSetAttribute(lstm_kernel,   cudaFuncAttributeMaxDynamicSharedMemorySize, LSTM_SMEM);

  const int ROWS = TT*BB; // 6144

  // 1: fused setup (inits + barrier reset + bias_ea + addressing)
  combo_kernel<<<NB_A + 128 + NC, 256>>>(q, r, hx0, cx0, b_ih, b_hh, W_a,
                                         W_e, W_add, b_a, b_e, b_add, Mk, k_tab);
  // 2: Aea/Bea in one launch                 (2 x 1024 x 512)
  sgemm2_dual_k<<<dim3(8,8), 256>>>(S->Sw, S->WaT, S->Wa2T, S->Aea, S->Bea);
  // 3: eaproj_t + kproj_t fused              (320 blocks)
  proj_fused_k<<<320, 256>>>(k_tab, x_tab, W_f, b_f);
  // 4-6: persistent memory recurrence x3 (DIAGNOSTIC: idempotent replicas;
  //      M = (dur - dur_prev)/2 isolates memrec phase time)
  memrec_kernel<<<128, 512, MEMREC_SMEM>>>(Mv0, W_f, 0*8*MSLOTS);
  memrec_kernel<<<128, 512, MEMREC_SMEM>>>(Mv0, W_f, 1*8*MSLOTS);
  memrec_kernel<<<128, 512, MEMREC_SMEM>>>(Mv0, W_f, 2*8*MSLOTS);
  // 7: hop-source search
  src_kernel<<<BB, 64>>>();
  // 8: xproj = f @ W_ih^T + (b_ih + b_hh)    (6144 x 2048)
  sgemm2_k<true><<<dim3(48,16), 256>>>(S->f, ROWS, W_ih, DD, S->bihh, S->xproj, 4*DD);
  // 9: persistent hop-LSTM (register-tiled)
  lstm_kernel<<<128, 256, LSTM_SMEM>>>(W_hh);
  // 10: head
  head_kernel<<<(BB*TT*32 + 255)/256, 256>>>(W_p, b_p, out);
}

// round 12
// speedup vs baseline: 1.8989x; 1.8989x over previous
#include <cuda_runtime.h>
#include <math.h>

#define BB 128
#define TT 48
#define DD 512
#define MM 64
#define NC 2000

typedef unsigned long long u64;

// ---------------- f32x2 packed helpers (sm_100+) -----------------------------
__device__ __forceinline__ u64 ffma2(u64 a, u64 b, u64 c){
  u64 d; asm("fma.rn.f32x2 %0, %1, %2, %3;" : "=l"(d) : "l"(a), "l"(b), "l"(c));
  return d;
}
__device__ __forceinline__ u64 f2pack(float lo, float hi){
  u64 r; asm("mov.b64 %0, {%1, %2};" : "=l"(r) : "f"(lo), "f"(hi)); return r;
}
__device__ __forceinline__ void f2unp(u64 v, float& lo, float& hi){
  asm("mov.b64 {%0, %1}, %2;" : "=f"(lo), "=f"(hi) : "l"(v));
}
__device__ __forceinline__ float f2sum(u64 v){
  float lo, hi; f2unp(v, lo, hi); return lo + hi;
}

// ---------------- static device scratch --------------------------------------
struct Scratch {
  float w_table[NC*MM];
  unsigned long long sig_table[NC*2];
  float kproj_t[2048*DD];
  float eaproj_t[4096*2*DD];
  float Aea[2*DD*DD];
  float Bea[2*DD*DD];
  float Sw[2*DD*DD];
  float WaT[DD*DD];
  float Wa2T[DD*DD];
  float bias_ea[2*DD];
  float rd[BB*DD];
  float f[TT*BB*DD];
  float ea[BB*2*DD];
  float xproj[TT*BB*4*DD];
  float H[(TT+1)*BB*DD];
  float C[(TT+1)*BB*DD];
  float bihh[4*DD];
  int src[TT*BB];
  int qidx[TT*BB];                // layout t*BB + b
  int xidx[TT*BB];
};
__device__ Scratch gS;

// barrier counters: memrec 8 groups x 144 slots, lstm 4 x 48
#define MSLOTS 144
__device__ unsigned gBarM[8*MSLOTS];
__device__ unsigned gBarL[4*TT];

__device__ __forceinline__ float sigm(float x){ return 1.f/(1.f+expf(-x)); }

// Group barrier, cheap-correct idiom:
//   arrival: atom.add.release.gpu  (orders this block's prior stores)
//   wait:    RELAXED spin (no per-poll L1 invalidation)
//   then:    ONE fence.acq_rel.gpu (fence-based synchronization: the relaxed
//            load that observed the release-store, followed by an acquire
//            fence, orders all subsequent loads; bar.sync extends to the CTA)
__device__ __forceinline__ void gbar_g(unsigned* ctr, int slot, unsigned nb){
  __syncthreads();
  if (threadIdx.x == 0){
    unsigned prev;
    asm volatile("atom.add.release.gpu.u32 %0, [%1], 1;"
                 : "=r"(prev) : "l"(ctr + slot) : "memory");
    if (prev + 1u < nb){
      unsigned v = 0, it = 0;
      do {
        asm volatile("ld.relaxed.gpu.u32 %0, [%1];"
                     : "=r"(v) : "l"(ctr + slot) : "memory");
      } while (v < nb && ++it < 4000000u);
    }
    asm volatile("fence.acq_rel.gpu;" ::: "memory");
  }
  __syncthreads();
}

// ---------------- combo setup kernel ----------------------------------------
#define EW_HC    (BB*DD)            // 65536
#define EW_IDX   (TT*BB)            // 6144
#define EW_BIHH  (4*DD)             // 2048
#define EW_TRANS (DD*DD)            // 262144
#define EW_STACK (DD*DD)            // 262144
#define EW_BARS  (8*MSLOTS + 4*TT)
#define EW_TOTAL (EW_HC+EW_IDX+EW_BIHH+EW_TRANS+EW_STACK+EW_BARS)
#define NB_A ((EW_TOTAL + 255)/256)

__global__ __launch_bounds__(256) void combo_kernel(
    const int* __restrict__ q, const int* __restrict__ r,
    const float* __restrict__ hx0, const float* __restrict__ cx0,
    const float* __restrict__ bih, const float* __restrict__ bhh,
    const float* __restrict__ Wa,
    const float* __restrict__ We, const float* __restrict__ Wadd,
    const float* __restrict__ ba, const float* __restrict__ be,
    const float* __restrict__ badd,
    const float* __restrict__ Mk, const float* __restrict__ k_table)
{
  int blk = blockIdx.x;
  int tid = threadIdx.x;
  if (blk < NB_A){
    int i = blk*256 + tid;
    if (i < EW_HC){
      gS.H[i] = hx0[i % DD]; gS.C[i] = cx0[i % DD];
    } else if ((i -= EW_HC) < EW_IDX){
      int t = i / BB, b = i % BB;
      int qi = q[b*TT + t];
      int ri = r[b*TT + t];
      gS.qidx[i] = qi;
      gS.xidx[i] = qi + NC*ri;
    } else if ((i -= EW_IDX) < EW_BIHH){
      gS.bihh[i] = bih[i] + bhh[i];
    } else if ((i -= EW_BIHH) < EW_TRANS){
      int j = i / DD, k = i % DD;
      gS.WaT[i]  = Wa[(long)k*(2*DD) + j];
      gS.Wa2T[i] = Wa[(long)k*(2*DD) + DD + j];
    } else if ((i -= EW_TRANS) < EW_STACK){
      gS.Sw[i] = We[i]; gS.Sw[DD*DD + i] = Wadd[i];
    } else if ((i -= EW_STACK) < EW_BARS){
      if (i < 8*MSLOTS) gBarM[i] = 0u; else gBarL[i - 8*MSLOTS] = 0u;
    }
    return;
  }
  blk -= NB_A;
  if (blk < 128){
    int n = blk*8 + (tid >> 5);
    int lane = tid & 31;
    const float* row = (n < DD) ? (We + (long)n*DD) : (Wadd + (long)(n-DD)*DD);
    float s = 0.f;
    for (int k = lane; k < DD; k += 32) s += row[k]*ba[k];
    #pragma unroll
    for (int o = 16; o > 0; o >>= 1) s += __shfl_down_sync(0xffffffffu, s, o);
    if (lane == 0) gS.bias_ea[n] = s + ((n < DD) ? be[n] : badd[n-DD]);
    return;
  }
  blk -= 128;
  // ---- addressing softmax + signature for q id = blk ----
  {
    int id = blk;
    __shared__ float kv[DD];
    __shared__ float lg[MM];
    __shared__ float eg[MM];
    __shared__ unsigned char ivb[MM];
    const float* kr = k_table + (long)id*DD;
    kv[tid] = kr[tid]; kv[tid+256] = kr[tid+256];
    __syncthreads();
    int m = tid >> 2, part = tid & 3;
    const ulonglong2* mk2 = (const ulonglong2*)(Mk + (long)m*DD + part*128);
    const ulonglong2* kv2 = (const ulonglong2*)(kv + part*128);
    u64 acc2 = 0;
    #pragma unroll 8
    for (int k4 = 0; k4 < 32; k4++){
      ulonglong2 m2 = mk2[k4], k2 = kv2[k4];
      acc2 = ffma2(m2.x, k2.x, acc2);
      acc2 = ffma2(m2.y, k2.y, acc2);
    }
    float s = f2sum(acc2);
    s += __shfl_down_sync(0xffffffffu, s, 2, 4);
    s += __shfl_down_sync(0xffffffffu, s, 1, 4);
    if (part == 0) lg[m] = s;
    __syncthreads();
    if (tid < MM){
      float sv = lg[tid];
      float mx = -1e30f;
      for (int mm = 0; mm < MM; mm++) mx = fmaxf(mx, lg[mm]);
      eg[tid] = expf(sv - mx);
    }
    __syncthreads();
    if (tid < MM){
      float sum = 0.f;
      for (int mm = 0; mm < MM; mm++) sum += eg[mm];
      float wv = eg[tid] / sum;
      gS.w_table[(long)id*MM + tid] = wv;
      float mval = fminf((wv - 0.075f)/(0.088f - 0.075f), (1.0f - wv)/(1.0f - 0.088f));
      mval = fmaxf(mval, 0.f);
      int iv = (mval >= 0.6f) ? 2 : ((mval >= 0.1f) ? 1 : 0);
      ivb[tid] = (unsigned char)iv;
    }
    __syncthreads();
    if (tid < 2){
      unsigned long long sg = 0ull;
      #pragma unroll
      for (int i2 = 0; i2 < 32; i2++) sg |= ((unsigned long long)ivb[tid*32 + i2]) << (2*i2);
      gS.sig_table[(long)id*2 + tid] = sg;
    }
  }
}

__global__ void src_kernel(){
  int b = blockIdx.x;
  int tid = threadIdx.x;  // 64 threads
  __shared__ unsigned long long s0[TT], s1[TT];
  if (tid < TT){
    int id = gS.qidx[tid*BB + b];
    s0[tid] = gS.sig_table[(long)id*2];
    s1[tid] = gS.sig_table[(long)id*2 + 1];
  }
  __syncthreads();
  if (tid < TT){
    int i = tid, sr = i - 1;
    unsigned long long a0 = s0[i], a1 = s1[i];
    for (int j = i - 1; j >= 0; j--){
      if (s0[j] == a0 && s1[j] == a1){ sr = j; break; }
    }
    gS.src[i*BB + b] = sr;
  }
}

// ---------------- double-buffered 128x128x8 SGEMM body ----------------------
template<bool HB>
__device__ __forceinline__ void sgemm_body(
    const float* __restrict__ A, int Mrows,
    const float* __restrict__ W, int ldw,
    const float* __restrict__ bias,
    float* __restrict__ C, int ldc,
    int m0, int n0)
{
  __shared__ u64 As2[2][8][128];
  __shared__ float Bs[2][8][128];
  int tid = threadIdx.x;
  int tx = tid & 15, ty = tid >> 4;
  int lr = tid >> 1;
  int lk = (tid & 1) * 4;
  int mrow = m0 + lr;
  int mload = mrow < Mrows ? mrow : (Mrows - 1);
  const float4* Ap = (const float4*)(A + (long)mload*DD + lk);
  const float4* Wp = (const float4*)(W + (long)(n0 + lr)*ldw + lk);

  u64 acc2[8][4];
  #pragma unroll
  for (int i = 0; i < 8; i++)
    #pragma unroll
    for (int j = 0; j < 4; j++) acc2[i][j] = 0ull;

  float4 av = Ap[0];
  float4 bv = Wp[0];
  As2[0][lk+0][lr] = f2pack(av.x, av.x);
  As2[0][lk+1][lr] = f2pack(av.y, av.y);
  As2[0][lk+2][lr] = f2pack(av.z, av.z);
  As2[0][lk+3][lr] = f2pack(av.w, av.w);
  Bs[0][lk+0][lr] = bv.x; Bs[0][lk+1][lr] = bv.y;
  Bs[0][lk+2][lr] = bv.z; Bs[0][lk+3][lr] = bv.w;
  __syncthreads();

  for (int kb = 0; kb < 64; kb++){
    int cur = kb & 1, nxt = cur ^ 1;
    if (kb < 63){
      av = Ap[(kb+1)*2];
      bv = Wp[(kb+1)*2];
    }
    #pragma unroll
    for (int k = 0; k < 8; k++){
      const ulonglong2* a4 = (const ulonglong2*)&As2[cur][k][ty*8];
      ulonglong2 t0 = a4[0], t1 = a4[1], t2 = a4[2], t3 = a4[3];
      u64 a2[8] = {t0.x, t0.y, t1.x, t1.y, t2.x, t2.y, t3.x, t3.y};
      float4 bl = *(const float4*)&Bs[cur][k][tx*8];
      float4 bh = *(const float4*)&Bs[cur][k][tx*8+4];
      u64 b2[4] = {f2pack(bl.x, bl.y), f2pack(bl.z, bl.w),
                   f2pack(bh.x, bh.y), f2pack(bh.z, bh.w)};
      #pragma unroll
      for (int i = 0; i < 8; i++)
        #pragma unroll
        for (int j = 0; j < 4; j++) acc2[i][j] = ffma2(a2[i], b2[j], acc2[i][j]);
    }
    if (kb < 63){
      As2[nxt][lk+0][lr] = f2pack(av.x, av.x);
      As2[nxt][lk+1][lr] = f2pack(av.y, av.y);
      As2[nxt][lk+2][lr] = f2pack(av.z, av.z);
      As2[nxt][lk+3][lr] = f2pack(av.w, av.w);
      Bs[nxt][lk+0][lr] = bv.x; Bs[nxt][lk+1][lr] = bv.y;
      Bs[nxt][lk+2][lr] = bv.z; Bs[nxt][lk+3][lr] = bv.w;
    }
    __syncthreads();
  }
  #pragma unroll
  for (int i = 0; i < 8; i++){
    int m = m0 + ty*8 + i;
    if (m < Mrows){
      int n = n0 + tx*8;
      float c0,c1,c2,c3,c4,c5,c6,c7;
      f2unp(acc2[i][0], c0, c1); f2unp(acc2[i][1], c2, c3);
      f2unp(acc2[i][2], c4, c5); f2unp(acc2[i][3], c6, c7);
      float4 o0, o1;
      o0.x = c0 + (HB ? bias[n+0] : 0.f);
      o0.y = c1 + (HB ? bias[n+1] : 0.f);
      o0.z = c2 + (HB ? bias[n+2] : 0.f);
      o0.w = c3 + (HB ? bias[n+3] : 0.f);
      o1.x = c4 + (HB ? bias[n+4] : 0.f);
      o1.y = c5 + (HB ? bias[n+5] : 0.f);
      o1.z = c6 + (HB ? bias[n+6] : 0.f);
      o1.w = c7 + (HB ? bias[n+7] : 0.f);
      *(float4*)(C + (long)m*ldc + n)     = o0;
      *(float4*)(C + (long)m*ldc + n + 4) = o1;
    }
  }
}

template<bool HB>
__global__ __launch_bounds__(256,2) void sgemm2_k(
    const float* __restrict__ A, int Mrows,
    const float* __restrict__ W, int ldw,
    const float* __restrict__ bias,
    float* __restrict__ C, int ldc)
{
  sgemm_body<HB>(A, Mrows, W, ldw, bias, C, ldc, blockIdx.x*128, blockIdx.y*128);
}

// Dual GEMM: blockIdx.y < 4 -> Aea = Sw @ WaT^T ; else -> Bea = Sw @ Wa2T^T
__global__ __launch_bounds__(256,2) void sgemm2_dual_k(
    const float* __restrict__ Sw,
    const float* __restrict__ W0, const float* __restrict__ W1,
    float* __restrict__ C0, float* __restrict__ C1)
{
  int by = blockIdx.y;
  if (by < 4)
    sgemm_body<false>(Sw, 1024, W0, DD, nullptr, C0, DD, blockIdx.x*128, by*128);
  else
    sgemm_body<false>(Sw, 1024, W1, DD, nullptr, C1, DD, blockIdx.x*128, (by-4)*128);
}

// Fused projection GEMM: blocks [0,256) -> eaproj_t, [256,320) -> kproj_t.
__global__ __launch_bounds__(256,2) void proj_fused_k(
    const float* __restrict__ k_tab, const float* __restrict__ x_tab,
    const float* __restrict__ W_f, const float* __restrict__ b_f)
{
  int blk = blockIdx.x;
  if (blk < 256){
    sgemm_body<true>(x_tab, 2*NC+1, gS.Bea, DD, gS.bias_ea, gS.eaproj_t, 2*DD,
                     (blk & 31)*128, (blk >> 5)*128);
  } else {
    int i = blk - 256;
    sgemm_body<true>(k_tab, NC, W_f + DD, 2*DD, b_f, gS.kproj_t, DD,
                     (i & 15)*128, (i >> 4)*128);
  }
}

// ---------------- persistent memory recurrence ------------------------------
#define MEMREC_SMEM ((MM*DD + 16*516 + 128)*4)

__global__ __launch_bounds__(512) void memrec_kernel(
    const float* __restrict__ Mv0, const float* __restrict__ W_f)
{
  extern __shared__ float sm[];
  float* mem_s = sm;                 // 64*512
  float* tile  = sm + MM*DD;         // 16*516
  float* w0s   = tile + 16*516;      // 64
  float* w1s   = w0s + 64;           // 64
  int bid = blockIdx.x, tid = threadIdx.x;
  int bq = bid >> 4, cq = bid & 15;
  int b0 = bq * 16;
  int myb = bid;
  unsigned* ctr = gBarM + bq*MSLOTS;

  {
    const float4* s4 = (const float4*)Mv0;
    float4* d4 = (float4*)mem_s;
    #pragma unroll 4
    for (int i = tid; i < MM*DD/4; i += 512) d4[i] = s4[i];
  }
  if (tid < MM){
    int qid = gS.qidx[myb];   // t = 0
    w0s[tid] = gS.w_table[(long)qid*MM + tid];
  }
  __syncthreads();
  {
    int d = tid;
    float acc = 0.f;
    #pragma unroll 8
    for (int m = 0; m < MM; m++) acc += w0s[m]*mem_s[m*DD + d];
    gS.rd[myb*DD + d] = acc;
  }
  int slot = 0;
  gbar_g(ctr, slot++, 16);

  for (int t = 0; t < TT; t++){
    // ---- stage1: f_t = tanh(Wf1 @ rd + kproj_table[q]) ----
    {
      for (int i = tid; i < 16*DD/4; i += 512){
        int rr = i >> 7, k4 = i & 127;
        *(float4*)(tile + rr*516 + k4*4) =
            __ldcg((const float4*)(gS.rd + (b0+rr)*DD) + k4);
      }
      __syncthreads();
      int bl = tid & 15, cl = tid >> 4;
      int c = cq*32 + cl;
      const ulonglong2* wr2 = (const ulonglong2*)(W_f + (long)c*(2*DD));
      const ulonglong2* rv2 = (const ulonglong2*)(tile + bl*516);
      u64 acc2 = 0;
      #pragma unroll 8
      for (int k4 = 0; k4 < 128; k4++){
        ulonglong2 wv = wr2[k4], rv = rv2[k4];
        acc2 = ffma2(wv.x, rv.x, acc2);
        acc2 = ffma2(wv.y, rv.y, acc2);
      }
      int brow = b0 + bl;
      int qid = gS.qidx[t*BB + brow];
      float acc = f2sum(acc2) + gS.kproj_t[(long)qid*DD + c];
      gS.f[((long)t*BB + brow)*DD + c] = tanhf(acc);
    }
    if (t == TT-1) break;
    gbar_g(ctr, slot++, 16);

    // ---- stage2: [e|a]_t = act(Aea @ f_t + eaproj_table[x]) ----
    {
      for (int i = tid; i < 16*DD/4; i += 512){
        int rr = i >> 7, k4 = i & 127;
        *(float4*)(tile + rr*516 + k4*4) =
            __ldcg((const float4*)(gS.f + ((long)t*BB + b0 + rr)*DD) + k4);
      }
      __syncthreads();
      int bl = tid & 15, cp = tid >> 4;
      int c0 = cq*64 + cp*2;
      const ulonglong2* a0 = (const ulonglong2*)(gS.Aea + (long)c0*DD);
      const ulonglong2* a1 = (const ulonglong2*)(gS.Aea + (long)(c0+1)*DD);
      const ulonglong2* fv2 = (const ulonglong2*)(tile + bl*516);
      u64 acc0_2 = 0, acc1_2 = 0;
      #pragma unroll 8
      for (int k4 = 0; k4 < 128; k4++){
        ulonglong2 fv = fv2[k4];
        ulonglong2 w0v = a0[k4], w1v = a1[k4];
        acc0_2 = ffma2(w0v.x, fv.x, acc0_2);
        acc0_2 = ffma2(w0v.y, fv.y, acc0_2);
        acc1_2 = ffma2(w1v.x, fv.x, acc1_2);
        acc1_2 = ffma2(w1v.y, fv.y, acc1_2);
      }
      int brow = b0 + bl;
      int xid = gS.xidx[t*BB + brow];
      const float* ep = gS.eaproj_t + (long)xid*(2*DD);
      float v0 = f2sum(acc0_2) + ep[c0];
      float v1 = f2sum(acc1_2) + ep[c0+1];
      float* eo = gS.ea + brow*(2*DD);
      if (cq < 8){ eo[c0] = sigm(v0); eo[c0+1] = sigm(v1); }
      else       { eo[c0] = tanhf(v0); eo[c0+1] = tanhf(v1); }
    }
    gbar_g(ctr, slot++, 16);

    // ---- stage3: mem update (SMEM-resident) + rd_{t+1} ----
    {
      if (tid < MM){
        int q0 = gS.qidx[t*BB + myb];
        int q1 = gS.qidx[(t+1)*BB + myb];
        w0s[tid] = gS.w_table[(long)q0*MM + tid];
        w1s[tid] = gS.w_table[(long)q1*MM + tid];
      }
      __syncthreads();
      int d = tid;
      float ev = __ldcg(&gS.ea[myb*(2*DD) + d]);
      float av = __ldcg(&gS.ea[myb*(2*DD) + DD + d]);
      float acc = 0.f;
      #pragma unroll 8
      for (int m = 0; m < MM; m++){
        float v = mem_s[m*DD + d];
        v = v*(1.f - w0s[m]*ev) + w0s[m]*av;
        mem_s[m*DD + d] = v;
        acc += w1s[m]*v;
      }
      gS.rd[myb*DD + d] = acc;
    }
    gbar_g(ctr, slot++, 16);
  }
}

// ---------------- persistent hop-LSTM (register-tiled, transposed H) --------
#define LSTM_SMEM ((64*516 + 512*32)*4)

__global__ __launch_bounds__(256) void lstm_kernel(const float* __restrict__ Whh){
  extern __shared__ float sm[];
  float* Ws  = sm;                 // 64 rows (o=(g<<4)|n) x 516
  float* HsT = sm + 64*516;        // [512 k][32 b]
  float* red = HsT;                // alias after k-loop: [4 ks][32 b][64 o]
  __shared__ int ssrc[32];
  int bid = blockIdx.x, tid = threadIdx.x;
  int n0 = (bid & 31) * 16;
  int b0 = (bid >> 5) * 32;
  unsigned* ctr = gBarL + (bid >> 5)*TT;

  {
    float4* WsV = (float4*)Ws;
    const float4* WhhV = (const float4*)Whh;
    for (int i = tid; i < 64*128; i += 256){
      int o = i >> 7, k4 = i & 127;
      int g = o >> 4, n = o & 15;
      WsV[o*129 + k4] = WhhV[(long)(g*DD + n0 + n)*128 + k4];
    }
  }
  __syncthreads();

  int og = tid & 7;
  int bg = (tid >> 3) & 7;
  int ks = tid >> 6;
  const ulonglong2* WsU = (const ulonglong2*)Ws;

  for (int t = 0; t < TT; t++){
    if (tid < 32) ssrc[tid] = gS.src[t*BB + b0 + tid];
    __syncthreads();
    for (int i = tid; i < 32*128; i += 256){
      int b = i & 31, k4 = i >> 5;
      long hrow = ((long)(ssrc[b]+1)*BB + (b0 + b))*DD;
      float4 hv = __ldcg((const float4*)(gS.H + hrow) + k4);
      int kb = k4*4;
      HsT[(kb+0)*32 + b] = hv.x;
      HsT[(kb+1)*32 + b] = hv.y;
      HsT[(kb+2)*32 + b] = hv.z;
      HsT[(kb+3)*32 + b] = hv.w;
    }
    __syncthreads();

    u64 acc[4][8];
    #pragma unroll
    for (int i2 = 0; i2 < 4; i2++)
      #pragma unroll
      for (int j = 0; j < 8; j++) acc[i2][j] = 0ull;

    int kb0 = ks*32;
    #pragma unroll 2
    for (int it = 0; it < 32; it++){
      int k4 = kb0 + it;
      int kw = k4*4;
      float4 h0 = *(const float4*)&HsT[(kw+0)*32 + bg*4];
      float4 h1 = *(const float4*)&HsT[(kw+1)*32 + bg*4];
      float4 h2 = *(const float4*)&HsT[(kw+2)*32 + bg*4];
      float4 h3 = *(const float4*)&HsT[(kw+3)*32 + bg*4];
      u64 p01[4], p23[4];
      p01[0] = f2pack(h0.x, h1.x); p01[1] = f2pack(h0.y, h1.y);
      p01[2] = f2pack(h0.z, h1.z); p01[3] = f2pack(h0.w, h1.w);
      p23[0] = f2pack(h2.x, h3.x); p23[1] = f2pack(h2.y, h3.y);
      p23[2] = f2pack(h2.z, h3.z); p23[3] = f2pack(h2.w, h3.w);
      #pragma unroll
      for (int j = 0; j < 8; j++){
        ulonglong2 wv = WsU[(long)(j*8 + og)*129 + k4];
        #pragma unroll
        for (int i2 = 0; i2 < 4; i2++){
          acc[i2][j] = ffma2(wv.x, p01[i2], acc[i2][j]);
          acc[i2][j] = ffma2(wv.y, p23[i2], acc[i2][j]);
        }
      }
    }
    __syncthreads();

    #pragma unroll
    for (int i2 = 0; i2 < 4; i2++){
      int b = bg*4 + i2;
      #pragma unroll
      for (int j = 0; j < 8; j++)
        red[((ks*32) + b)*64 + (j*8 + og)] = f2sum(acc[i2][j]);
    }
    __syncthreads();

    #pragma unroll
    for (int e = 0; e < 2; e++){
      int p = tid*2 + e;
      int b = p >> 4, n = p & 15;
      float g4[4];
      #pragma unroll
      for (int g = 0; g < 4; g++){
        int o = g*16 + n;
        g4[g] = red[(0*32 + b)*64 + o] + red[(1*32 + b)*64 + o]
              + red[(2*32 + b)*64 + o] + red[(3*32 + b)*64 + o];
      }
      const float* xp = gS.xproj + ((long)t*BB + b0 + b)*(4*DD);
      float gi = g4[0] + xp[n0 + n];
      float gf = g4[1] + xp[DD + n0 + n];
      float gg = g4[2] + xp[2*DD + n0 + n];
      float go = g4[3] + xp[3*DD + n0 + n];
      int srcp = ssrc[b] + 1;
      float cin = __ldcg(&gS.C[((long)srcp*BB + b0 + b)*DD + n0 + n]);
      float c = sigm(gf)*cin + sigm(gi)*tanhf(gg);
      float h = sigm(go)*tanhf(c);
      long o = ((long)(t+1)*BB + b0 + b)*DD + n0 + n;
      gS.H[o] = h;
      gS.C[o] = c;
    }
    if (t < TT-1) gbar_g(ctr, t, 32);
  }
}

// ---------------- prediction head -------------------------------------------
__global__ void head_kernel(const float* __restrict__ Wp, const float* __restrict__ bp,
                            float* __restrict__ out){
  int gw = (blockIdx.x*blockDim.x + threadIdx.x) >> 5;
  int lane = threadIdx.x & 31;
  if (gw >= BB*TT) return;
  int b = gw / TT, t = gw % TT;
  const float* h = gS.H + ((long)(t+1)*BB + b)*DD;
  float s = 0.f;
  for (int j = lane; j < DD; j += 32) s += h[j]*Wp[j];
  #pragma unroll
  for (int o = 16; o > 0; o >>= 1) s += __shfl_down_sync(0xffffffffu, s, o);
  if (lane == 0) out[b*TT + t] = sigm(s + bp[0]);
}

// ---------------- host orchestration ----------------------------------------
extern "C" void kernel_launch(void* const* d_in, const int* in_sizes, int n_in,
                              void* d_out, int out_size){
  (void)in_sizes; (void)n_in; (void)out_size;
  const int*   q     = (const int*)d_in[0];
  const int*   r     = (const int*)d_in[1];
  const float* Mk    = (const float*)d_in[2];
  const float* Mv0   = (const float*)d_in[3];
  const float* k_tab = (const float*)d_in[4];
  const float* x_tab = (const float*)d_in[5];
  const float* W_e   = (const float*)d_in[6];
  const float* b_e   = (const float*)d_in[7];
  const float* W_add = (const float*)d_in[8];
  const float* b_add = (const float*)d_in[9];
  const float* W_a   = (const float*)d_in[10];
  const float* b_a   = (const float*)d_in[11];
  const float* W_f   = (const float*)d_in[12];
  const float* b_f   = (const float*)d_in[13];
  const float* W_ih  = (const float*)d_in[14];
  const float* W_hh  = (const float*)d_in[15];
  const float* b_ih  = (const float*)d_in[16];
  const float* b_hh  = (const float*)d_in[17];
  const float* hx0   = (const float*)d_in[18];
  const float* cx0   = (const float*)d_in[19];
  const float* W_p   = (const float*)d_in[20];
  const float* b_p   = (const float*)d_in[21];
  float* out = (float*)d_out;

  Scratch* S = nullptr;
  cudaGetSymbolAddress((void**)&S, gS);

  cudaFuncSetAttribute(memrec_kernel, cudaFuncAttributeMaxDynamicSharedMemorySize, MEMREC_SMEM);
  cudaFuncSetAttribute(lstm_kernel,   cudaFuncAttributeMaxDynamicSharedMemorySize, LSTM_SMEM);

  const int ROWS = TT*BB; // 6144

  // 1: fused setup (inits + barrier reset + bias_ea + addressing)
  combo_kernel<<<NB_A + 128 + NC, 256>>>(q, r, hx0, cx0, b_ih, b_hh, W_a,
                                         W_e, W_add, b_a, b_e, b_add, Mk, k_tab);
  // 2: Aea/Bea in one launch                 (2 x 1024 x 512)
  sgemm2_dual_k<<<dim3(8,8), 256>>>(S->Sw, S->WaT, S->Wa2T, S->Aea, S->Bea);
  // 3: eaproj_t + kproj_t fused              (320 blocks)
  proj_fused_k<<<320, 256>>>(k_tab, x_tab, W_f, b_f);
  // 4: persistent memory recurrence  [profiled slot]
  memrec_kernel<<<128, 512, MEMREC_SMEM>>>(Mv0, W_f);
  // 5: hop-source search
  src_kernel<<<BB, 64>>>();
  // 6: xproj = f @ W_ih^T + (b_ih + b_hh)    (6144 x 2048)
  sgemm2_k<true><<<dim3(48,16), 256>>>(S->f, ROWS, W_ih, DD, S->bihh, S->xproj, 4*DD);
  // 7: persistent hop-LSTM (register-tiled)
  lstm_kernel<<<128, 256, LSTM_SMEM>>>(W_hh);
  // 8: head
  head_kernel<<<(BB*TT*32 + 255)/256, 256>>>(W_p, b_p, out);
}

// round 16
// speedup vs baseline: 2.1840x; 1.1501x over previous
#include <cuda_runtime.h>
#include <math.h>

#define BB 128
#define TT 48
#define DD 512
#define MM 64
#define NC 2000

typedef unsigned long long u64;

// ---------------- f32x2 packed helpers (sm_100+) -----------------------------
__device__ __forceinline__ u64 ffma2(u64 a, u64 b, u64 c){
  u64 d; asm("fma.rn.f32x2 %0, %1, %2, %3;" : "=l"(d) : "l"(a), "l"(b), "l"(c));
  return d;
}
__device__ __forceinline__ u64 f2pack(float lo, float hi){
  u64 r; asm("mov.b64 %0, {%1, %2};" : "=l"(r) : "f"(lo), "f"(hi)); return r;
}
__device__ __forceinline__ void f2unp(u64 v, float& lo, float& hi){
  asm("mov.b64 {%0, %1}, %2;" : "=f"(lo), "=f"(hi) : "l"(v));
}
__device__ __forceinline__ float f2sum(u64 v){
  float lo, hi; f2unp(v, lo, hi); return lo + hi;
}

// ---------------- static device scratch --------------------------------------
struct Scratch {
  float w_table[NC*MM];
  unsigned long long sig_table[NC*2];
  float kproj_t[2048*DD];
  float eaproj_t[4096*2*DD];
  float Aea[2*DD*DD];
  float Bea[2*DD*DD];
  float Sw[2*DD*DD];
  float WaT[DD*DD];
  float Wa2T[DD*DD];
  float bias_ea[2*DD];
  float rd[BB*DD];
  float f[TT*BB*DD];
  float ea[BB*2*DD];
  float xproj[TT*BB*4*DD];
  float H[(TT+1)*BB*DD];
  float C[(TT+1)*BB*DD];
  float bihh[4*DD];
  float mem[BB*MM*DD];            // value memory, L2-resident (cg access only)
  int src[TT*BB];
  int qidx[TT*BB];                // layout t*BB + b
  int xidx[TT*BB];
};
__device__ Scratch gS;

// barrier counters: memrec 8 groups x 144 slots, lstm 4 x 48
#define MSLOTS 144
__device__ unsigned gBarM[8*MSLOTS];
__device__ unsigned gBarL[4*TT];

__device__ __forceinline__ float sigm(float x){ return 1.f/(1.f+expf(-x)); }

// Group barrier: acq_rel atomic arrival + ld.acquire spin (round-7/10 protocol,
// proven correct at 3330us). The acquire's L1 invalidation is now harmless to
// the hot loops: weights live in SMEM, value memory accessed via L2 (cg).
__device__ __forceinline__ void gbar_g(unsigned* ctr, int slot, unsigned nb){
  __syncthreads();
  if (threadIdx.x == 0){
    unsigned prev;
    asm volatile("atom.add.acq_rel.gpu.u32 %0, [%1], 1;"
                 : "=r"(prev) : "l"(ctr + slot) : "memory");
    if (prev + 1u < nb){
      unsigned v = 0, it = 0;
      do {
        asm volatile("ld.acquire.gpu.u32 %0, [%1];"
                     : "=r"(v) : "l"(ctr + slot) : "memory");
      } while (v < nb && ++it < 2000000u);
    }
  }
  __syncthreads();
}

// ---------------- combo setup kernel ----------------------------------------
#define EW_HC    (BB*DD)            // 65536
#define EW_IDX   (TT*BB)            // 6144
#define EW_BIHH  (4*DD)             // 2048
#define EW_TRANS (DD*DD)            // 262144
#define EW_STACK (DD*DD)            // 262144
#define EW_BARS  (8*MSLOTS + 4*TT)
#define EW_TOTAL (EW_HC+EW_IDX+EW_BIHH+EW_TRANS+EW_STACK+EW_BARS)
#define NB_A ((EW_TOTAL + 255)/256)

__global__ __launch_bounds__(256) void combo_kernel(
    const int* __restrict__ q, const int* __restrict__ r,
    const float* __restrict__ hx0, const float* __restrict__ cx0,
    const float* __restrict__ bih, const float* __restrict__ bhh,
    const float* __restrict__ Wa,
    const float* __restrict__ We, const float* __restrict__ Wadd,
    const float* __restrict__ ba, const float* __restrict__ be,
    const float* __restrict__ badd,
    const float* __restrict__ Mk, const float* __restrict__ k_table)
{
  int blk = blockIdx.x;
  int tid = threadIdx.x;
  if (blk < NB_A){
    int i = blk*256 + tid;
    if (i < EW_HC){
      gS.H[i] = hx0[i % DD]; gS.C[i] = cx0[i % DD];
    } else if ((i -= EW_HC) < EW_IDX){
      int t = i / BB, b = i % BB;
      int qi = q[b*TT + t];
      int ri = r[b*TT + t];
      gS.qidx[i] = qi;
      gS.xidx[i] = qi + NC*ri;
    } else if ((i -= EW_IDX) < EW_BIHH){
      gS.bihh[i] = bih[i] + bhh[i];
    } else if ((i -= EW_BIHH) < EW_TRANS){
      int j = i / DD, k = i % DD;
      gS.WaT[i]  = Wa[(long)k*(2*DD) + j];
      gS.Wa2T[i] = Wa[(long)k*(2*DD) + DD + j];
    } else if ((i -= EW_TRANS) < EW_STACK){
      gS.Sw[i] = We[i]; gS.Sw[DD*DD + i] = Wadd[i];
    } else if ((i -= EW_STACK) < EW_BARS){
      if (i < 8*MSLOTS) gBarM[i] = 0u; else gBarL[i - 8*MSLOTS] = 0u;
    }
    return;
  }
  blk -= NB_A;
  if (blk < 128){
    int n = blk*8 + (tid >> 5);
    int lane = tid & 31;
    const float* row = (n < DD) ? (We + (long)n*DD) : (Wadd + (long)(n-DD)*DD);
    float s = 0.f;
    for (int k = lane; k < DD; k += 32) s += row[k]*ba[k];
    #pragma unroll
    for (int o = 16; o > 0; o >>= 1) s += __shfl_down_sync(0xffffffffu, s, o);
    if (lane == 0) gS.bias_ea[n] = s + ((n < DD) ? be[n] : badd[n-DD]);
    return;
  }
  blk -= 128;
  // ---- addressing softmax + signature for q id = blk ----
  {
    int id = blk;
    __shared__ float kv[DD];
    __shared__ float lg[MM];
    __shared__ float eg[MM];
    __shared__ unsigned char ivb[MM];
    const float* kr = k_table + (long)id*DD;
    kv[tid] = kr[tid]; kv[tid+256] = kr[tid+256];
    __syncthreads();
    int m = tid >> 2, part = tid & 3;
    const ulonglong2* mk2 = (const ulonglong2*)(Mk + (long)m*DD + part*128);
    const ulonglong2* kv2 = (const ulonglong2*)(kv + part*128);
    u64 acc2 = 0;
    #pragma unroll 8
    for (int k4 = 0; k4 < 32; k4++){
      ulonglong2 m2 = mk2[k4], k2 = kv2[k4];
      acc2 = ffma2(m2.x, k2.x, acc2);
      acc2 = ffma2(m2.y, k2.y, acc2);
    }
    float s = f2sum(acc2);
    s += __shfl_down_sync(0xffffffffu, s, 2, 4);
    s += __shfl_down_sync(0xffffffffu, s, 1, 4);
    if (part == 0) lg[m] = s;
    __syncthreads();
    if (tid < MM){
      float sv = lg[tid];
      float mx = -1e30f;
      for (int mm = 0; mm < MM; mm++) mx = fmaxf(mx, lg[mm]);
      eg[tid] = expf(sv - mx);
    }
    __syncthreads();
    if (tid < MM){
      float sum = 0.f;
      for (int mm = 0; mm < MM; mm++) sum += eg[mm];
      float wv = eg[tid] / sum;
      gS.w_table[(long)id*MM + tid] = wv;
      float mval = fminf((wv - 0.075f)/(0.088f - 0.075f), (1.0f - wv)/(1.0f - 0.088f));
      mval = fmaxf(mval, 0.f);
      int iv = (mval >= 0.6f) ? 2 : ((mval >= 0.1f) ? 1 : 0);
      ivb[tid] = (unsigned char)iv;
    }
    __syncthreads();
    if (tid < 2){
      unsigned long long sg = 0ull;
      #pragma unroll
      for (int i2 = 0; i2 < 32; i2++) sg |= ((unsigned long long)ivb[tid*32 + i2]) << (2*i2);
      gS.sig_table[(long)id*2 + tid] = sg;
    }
  }
}

__global__ void src_kernel(){
  int b = blockIdx.x;
  int tid = threadIdx.x;  // 64 threads
  __shared__ unsigned long long s0[TT], s1[TT];
  if (tid < TT){
    int id = gS.qidx[tid*BB + b];
    s0[tid] = gS.sig_table[(long)id*2];
    s1[tid] = gS.sig_table[(long)id*2 + 1];
  }
  __syncthreads();
  if (tid < TT){
    int i = tid, sr = i - 1;
    unsigned long long a0 = s0[i], a1 = s1[i];
    for (int j = i - 1; j >= 0; j--){
      if (s0[j] == a0 && s1[j] == a1){ sr = j; break; }
    }
    gS.src[i*BB + b] = sr;
  }
}

// ---------------- double-buffered 128x128x8 SGEMM body ----------------------
template<bool HB>
__device__ __forceinline__ void sgemm_body(
    const float* __restrict__ A, int Mrows,
    const float* __restrict__ W, int ldw,
    const float* __restrict__ bias,
    float* __restrict__ C, int ldc,
    int m0, int n0)
{
  __shared__ u64 As2[2][8][128];
  __shared__ float Bs[2][8][128];
  int tid = threadIdx.x;
  int tx = tid & 15, ty = tid >> 4;
  int lr = tid >> 1;
  int lk = (tid & 1) * 4;
  int mrow = m0 + lr;
  int mload = mrow < Mrows ? mrow : (Mrows - 1);
  const float4* Ap = (const float4*)(A + (long)mload*DD + lk);
  const float4* Wp = (const float4*)(W + (long)(n0 + lr)*ldw + lk);

  u64 acc2[8][4];
  #pragma unroll
  for (int i = 0; i < 8; i++)
    #pragma unroll
    for (int j = 0; j < 4; j++) acc2[i][j] = 0ull;

  float4 av = Ap[0];
  float4 bv = Wp[0];
  As2[0][lk+0][lr] = f2pack(av.x, av.x);
  As2[0][lk+1][lr] = f2pack(av.y, av.y);
  As2[0][lk+2][lr] = f2pack(av.z, av.z);
  As2[0][lk+3][lr] = f2pack(av.w, av.w);
  Bs[0][lk+0][lr] = bv.x; Bs[0][lk+1][lr] = bv.y;
  Bs[0][lk+2][lr] = bv.z; Bs[0][lk+3][lr] = bv.w;
  __syncthreads();

  for (int kb = 0; kb < 64; kb++){
    int cur = kb & 1, nxt = cur ^ 1;
    if (kb < 63){
      av = Ap[(kb+1)*2];
      bv = Wp[(kb+1)*2];
    }
    #pragma unroll
    for (int k = 0; k < 8; k++){
      const ulonglong2* a4 = (const ulonglong2*)&As2[cur][k][ty*8];
      ulonglong2 t0 = a4[0], t1 = a4[1], t2 = a4[2], t3 = a4[3];
      u64 a2[8] = {t0.x, t0.y, t1.x, t1.y, t2.x, t2.y, t3.x, t3.y};
      float4 bl = *(const float4*)&Bs[cur][k][tx*8];
      float4 bh = *(const float4*)&Bs[cur][k][tx*8+4];
      u64 b2[4] = {f2pack(bl.x, bl.y), f2pack(bl.z, bl.w),
                   f2pack(bh.x, bh.y), f2pack(bh.z, bh.w)};
      #pragma unroll
      for (int i = 0; i < 8; i++)
        #pragma unroll
        for (int j = 0; j < 4; j++) acc2[i][j] = ffma2(a2[i], b2[j], acc2[i][j]);
    }
    if (kb < 63){
      As2[nxt][lk+0][lr] = f2pack(av.x, av.x);
      As2[nxt][lk+1][lr] = f2pack(av.y, av.y);
      As2[nxt][lk+2][lr] = f2pack(av.z, av.z);
      As2[nxt][lk+3][lr] = f2pack(av.w, av.w);
      Bs[nxt][lk+0][lr] = bv.x; Bs[nxt][lk+1][lr] = bv.y;
      Bs[nxt][lk+2][lr] = bv.z; Bs[nxt][lk+3][lr] = bv.w;
    }
    __syncthreads();
  }
  #pragma unroll
  for (int i = 0; i < 8; i++){
    int m = m0 + ty*8 + i;
    if (m < Mrows){
      int n = n0 + tx*8;
      float c0,c1,c2,c3,c4,c5,c6,c7;
      f2unp(acc2[i][0], c0, c1); f2unp(acc2[i][1], c2, c3);
      f2unp(acc2[i][2], c4, c5); f2unp(acc2[i][3], c6, c7);
      float4 o0, o1;
      o0.x = c0 + (HB ? bias[n+0] : 0.f);
      o0.y = c1 + (HB ? bias[n+1] : 0.f);
      o0.z = c2 + (HB ? bias[n+2] : 0.f);
      o0.w = c3 + (HB ? bias[n+3] : 0.f);
      o1.x = c4 + (HB ? bias[n+4] : 0.f);
      o1.y = c5 + (HB ? bias[n+5] : 0.f);
      o1.z = c6 + (HB ? bias[n+6] : 0.f);
      o1.w = c7 + (HB ? bias[n+7] : 0.f);
      *(float4*)(C + (long)m*ldc + n)     = o0;
      *(float4*)(C + (long)m*ldc + n + 4) = o1;
    }
  }
}

template<bool HB>
__global__ __launch_bounds__(256,2) void sgemm2_k(
    const float* __restrict__ A, int Mrows,
    const float* __restrict__ W, int ldw,
    const float* __restrict__ bias,
    float* __restrict__ C, int ldc)
{
  sgemm_body<HB>(A, Mrows, W, ldw, bias, C, ldc, blockIdx.x*128, blockIdx.y*128);
}

// Dual GEMM: blockIdx.y < 4 -> Aea = Sw @ WaT^T ; else -> Bea = Sw @ Wa2T^T
__global__ __launch_bounds__(256,2) void sgemm2_dual_k(
    const float* __restrict__ Sw,
    const float* __restrict__ W0, const float* __restrict__ W1,
    float* __restrict__ C0, float* __restrict__ C1)
{
  int by = blockIdx.y;
  if (by < 4)
    sgemm_body<false>(Sw, 1024, W0, DD, nullptr, C0, DD, blockIdx.x*128, by*128);
  else
    sgemm_body<false>(Sw, 1024, W1, DD, nullptr, C1, DD, blockIdx.x*128, (by-4)*128);
}

// Fused projection GEMM: blocks [0,256) -> eaproj_t, [256,320) -> kproj_t.
__global__ __launch_bounds__(256,2) void proj_fused_k(
    const float* __restrict__ k_tab, const float* __restrict__ x_tab,
    const float* __restrict__ W_f, const float* __restrict__ b_f)
{
  int blk = blockIdx.x;
  if (blk < 256){
    sgemm_body<true>(x_tab, 2*NC+1, gS.Bea, DD, gS.bias_ea, gS.eaproj_t, 2*DD,
                     (blk & 31)*128, (blk >> 5)*128);
  } else {
    int i = blk - 256;
    sgemm_body<true>(k_tab, NC, W_f + DD, 2*DD, b_f, gS.kproj_t, DD,
                     (i & 15)*128, (i >> 4)*128);
  }
}

// ---------------- persistent memory recurrence (SMEM-resident weights) ------
// smem: Wf_s 32x512 (64KB) + Aea_s 64x512 (128KB) + tile 16x516 (33KB) + w0/w1.
// Weights loaded ONCE; immune to the barrier's L1 invalidation. Value memory
// lives in gS.mem, accessed exclusively via L2 (__ldcg/__stcg, coalesced).
#define MEMREC_SMEM ((32*DD + 64*DD + 16*516 + 128)*4)

__global__ __launch_bounds__(512) void memrec_kernel(
    const float* __restrict__ Mv0, const float* __restrict__ W_f)
{
  extern __shared__ float sm[];
  float* Wf_s  = sm;                   // 32 x 512
  float* Aea_s = sm + 32*DD;           // 64 x 512
  float* tile  = Aea_s + 64*DD;        // 16 x 516
  float* w0s   = tile + 16*516;        // 64
  float* w1s   = w0s + 64;             // 64
  int bid = blockIdx.x, tid = threadIdx.x;
  int bq = bid >> 4, cq = bid & 15;
  int b0 = bq * 16;
  int myb = bid;
  unsigned* ctr = gBarM + bq*MSLOTS;

  // ---- one-time: load weight slices into SMEM ----
  {
    float4* Wf4 = (float4*)Wf_s;
    for (int i = tid; i < 32*128; i += 512){
      int r = i >> 7, k4 = i & 127;
      Wf4[r*128 + k4] = ((const float4*)(W_f + (long)(cq*32 + r)*(2*DD)))[k4];
    }
    float4* Ae4 = (float4*)Aea_s;
    for (int i = tid; i < 64*128; i += 512){
      int r = i >> 7, k4 = i & 127;
      Ae4[r*128 + k4] = ((const float4*)(gS.Aea + (long)(cq*64 + r)*DD))[k4];
    }
  }
  // ---- one-time: init own value memory in L2 + read0 ----
  {
    float4* mb4 = (float4*)(gS.mem + (long)myb*MM*DD);
    const float4* s4 = (const float4*)Mv0;
    #pragma unroll 4
    for (int i = tid; i < MM*DD/4; i += 512) __stcg(mb4 + i, s4[i]);
  }
  if (tid < MM){
    int qid = gS.qidx[myb];   // t = 0
    w0s[tid] = gS.w_table[(long)qid*MM + tid];
  }
  __syncthreads();
  {
    int d = tid;
    float acc = 0.f;
    #pragma unroll 8
    for (int m = 0; m < MM; m++) acc += w0s[m]*Mv0[m*DD + d];
    gS.rd[myb*DD + d] = acc;
  }
  int slot = 0;
  gbar_g(ctr, slot++, 16);

  for (int t = 0; t < TT; t++){
    // ---- stage1: f_t = tanh(Wf1 @ rd + kproj_table[q]) ----
    {
      for (int i = tid; i < 16*DD/4; i += 512){
        int rr = i >> 7, k4 = i & 127;
        *(float4*)(tile + rr*516 + k4*4) =
            __ldcg((const float4*)(gS.rd + (b0+rr)*DD) + k4);
      }
      __syncthreads();
      int bl = tid & 15, cl = tid >> 4;
      int c = cq*32 + cl;
      const ulonglong2* wr2 = (const ulonglong2*)(Wf_s + cl*DD);
      const ulonglong2* rv2 = (const ulonglong2*)(tile + bl*516);
      u64 acc2 = 0;
      #pragma unroll 8
      for (int k4 = 0; k4 < 128; k4++){
        ulonglong2 wv = wr2[k4], rv = rv2[k4];
        acc2 = ffma2(wv.x, rv.x, acc2);
        acc2 = ffma2(wv.y, rv.y, acc2);
      }
      int brow = b0 + bl;
      int qid = gS.qidx[t*BB + brow];
      float acc = f2sum(acc2) + gS.kproj_t[(long)qid*DD + c];
      gS.f[((long)t*BB + brow)*DD + c] = tanhf(acc);
    }
    if (t == TT-1) break;
    gbar_g(ctr, slot++, 16);

    // ---- stage2: [e|a]_t = act(Aea @ f_t + eaproj_table[x]) ----
    {
      for (int i = tid; i < 16*DD/4; i += 512){
        int rr = i >> 7, k4 = i & 127;
        *(float4*)(tile + rr*516 + k4*4) =
            __ldcg((const float4*)(gS.f + ((long)t*BB + b0 + rr)*DD) + k4);
      }
      __syncthreads();
      int bl = tid & 15, cp = tid >> 4;
      int c0 = cq*64 + cp*2;
      const ulonglong2* a0 = (const ulonglong2*)(Aea_s + (cp*2)*DD);
      const ulonglong2* a1 = (const ulonglong2*)(Aea_s + (cp*2+1)*DD);
      const ulonglong2* fv2 = (const ulonglong2*)(tile + bl*516);
      u64 acc0_2 = 0, acc1_2 = 0;
      #pragma unroll 8
      for (int k4 = 0; k4 < 128; k4++){
        ulonglong2 fv = fv2[k4];
        ulonglong2 w0v = a0[k4], w1v = a1[k4];
        acc0_2 = ffma2(w0v.x, fv.x, acc0_2);
        acc0_2 = ffma2(w0v.y, fv.y, acc0_2);
        acc1_2 = ffma2(w1v.x, fv.x, acc1_2);
        acc1_2 = ffma2(w1v.y, fv.y, acc1_2);
      }
      int brow = b0 + bl;
      int xid = gS.xidx[t*BB + brow];
      const float* ep = gS.eaproj_t + (long)xid*(2*DD);
      float v0 = f2sum(acc0_2) + ep[c0];
      float v1 = f2sum(acc1_2) + ep[c0+1];
      float* eo = gS.ea + brow*(2*DD);
      if (cq < 8){ eo[c0] = sigm(v0); eo[c0+1] = sigm(v1); }
      else       { eo[c0] = tanhf(v0); eo[c0+1] = tanhf(v1); }
    }
    gbar_g(ctr, slot++, 16);

    // ---- stage3: mem update (L2-resident via cg) + rd_{t+1} ----
    {
      if (tid < MM){
        int q0 = gS.qidx[t*BB + myb];
        int q1 = gS.qidx[(t+1)*BB + myb];
        w0s[tid] = gS.w_table[(long)q0*MM + tid];
        w1s[tid] = gS.w_table[(long)q1*MM + tid];
      }
      __syncthreads();
      int d = tid;
      float ev = __ldcg(&gS.ea[myb*(2*DD) + d]);
      float av = __ldcg(&gS.ea[myb*(2*DD) + DD + d]);
      float* mb = gS.mem + (long)myb*MM*DD;
      float acc = 0.f;
      #pragma unroll 8
      for (int m = 0; m < MM; m++){
        float v = __ldcg(mb + m*DD + d);
        v = v*(1.f - w0s[m]*ev) + w0s[m]*av;
        __stcg(mb + m*DD + d, v);
        acc += w1s[m]*v;
      }
      gS.rd[myb*DD + d] = acc;
    }
    gbar_g(ctr, slot++, 16);
  }
}

// ---------------- persistent hop-LSTM (register-tiled, transposed H) --------
#define LSTM_SMEM ((64*516 + 512*32)*4)

__global__ __launch_bounds__(256) void lstm_kernel(const float* __restrict__ Whh){
  extern __shared__ float sm[];
  float* Ws  = sm;                 // 64 rows (o=(g<<4)|n) x 516
  float* HsT = sm + 64*516;        // [512 k][32 b]
  float* red = HsT;                // alias after k-loop: [4 ks][32 b][64 o]
  __shared__ int ssrc[32];
  int bid = blockIdx.x, tid = threadIdx.x;
  int n0 = (bid & 31) * 16;
  int b0 = (bid >> 5) * 32;
  unsigned* ctr = gBarL + (bid >> 5)*TT;

  {
    float4* WsV = (float4*)Ws;
    const float4* WhhV = (const float4*)Whh;
    for (int i = tid; i < 64*128; i += 256){
      int o = i >> 7, k4 = i & 127;
      int g = o >> 4, n = o & 15;
      WsV[o*129 + k4] = WhhV[(long)(g*DD + n0 + n)*128 + k4];
    }
  }
  __syncthreads();

  int og = tid & 7;
  int bg = (tid >> 3) & 7;
  int ks = tid >> 6;
  const ulonglong2* WsU = (const ulonglong2*)Ws;

  for (int t = 0; t < TT; t++){
    if (tid < 32) ssrc[tid] = gS.src[t*BB + b0 + tid];
    __syncthreads();
    for (int i = tid; i < 32*128; i += 256){
      int b = i & 31, k4 = i >> 5;
      long hrow = ((long)(ssrc[b]+1)*BB + (b0 + b))*DD;
      float4 hv = __ldcg((const float4*)(gS.H + hrow) + k4);
      int kb = k4*4;
      HsT[(kb+0)*32 + b] = hv.x;
      HsT[(kb+1)*32 + b] = hv.y;
      HsT[(kb+2)*32 + b] = hv.z;
      HsT[(kb+3)*32 + b] = hv.w;
    }
    __syncthreads();

    u64 acc[4][8];
    #pragma unroll
    for (int i2 = 0; i2 < 4; i2++)
      #pragma unroll
      for (int j = 0; j < 8; j++) acc[i2][j] = 0ull;

    int kb0 = ks*32;
    #pragma unroll 2
    for (int it = 0; it < 32; it++){
      int k4 = kb0 + it;
      int kw = k4*4;
      float4 h0 = *(const float4*)&HsT[(kw+0)*32 + bg*4];
      float4 h1 = *(const float4*)&HsT[(kw+1)*32 + bg*4];
      float4 h2 = *(const float4*)&HsT[(kw+2)*32 + bg*4];
      float4 h3 = *(const float4*)&HsT[(kw+3)*32 + bg*4];
      u64 p01[4], p23[4];
      p01[0] = f2pack(h0.x, h1.x); p01[1] = f2pack(h0.y, h1.y);
      p01[2] = f2pack(h0.z, h1.z); p01[3] = f2pack(h0.w, h1.w);
      p23[0] = f2pack(h2.x, h3.x); p23[1] = f2pack(h2.y, h3.y);
      p23[2] = f2pack(h2.z, h3.z); p23[3] = f2pack(h2.w, h3.w);
      #pragma unroll
      for (int j = 0; j < 8; j++){
        ulonglong2 wv = WsU[(long)(j*8 + og)*129 + k4];
        #pragma unroll
        for (int i2 = 0; i2 < 4; i2++){
          acc[i2][j] = ffma2(wv.x, p01[i2], acc[i2][j]);
          acc[i2][j] = ffma2(wv.y, p23[i2], acc[i2][j]);
        }
      }
    }
    __syncthreads();

    #pragma unroll
    for (int i2 = 0; i2 < 4; i2++){
      int b = bg*4 + i2;
      #pragma unroll
      for (int j = 0; j < 8; j++)
        red[((ks*32) + b)*64 + (j*8 + og)] = f2sum(acc[i2][j]);
    }
    __syncthreads();

    #pragma unroll
    for (int e = 0; e < 2; e++){
      int p = tid*2 + e;
      int b = p >> 4, n = p & 15;
      float g4[4];
      #pragma unroll
      for (int g = 0; g < 4; g++){
        int o = g*16 + n;
        g4[g] = red[(0*32 + b)*64 + o] + red[(1*32 + b)*64 + o]
              + red[(2*32 + b)*64 + o] + red[(3*32 + b)*64 + o];
      }
      const float* xp = gS.xproj + ((long)t*BB + b0 + b)*(4*DD);
      float gi = g4[0] + xp[n0 + n];
      float gf = g4[1] + xp[DD + n0 + n];
      float gg = g4[2] + xp[2*DD + n0 + n];
      float go = g4[3] + xp[3*DD + n0 + n];
      int srcp = ssrc[b] + 1;
      float cin = __ldcg(&gS.C[((long)srcp*BB + b0 + b)*DD + n0 + n]);
      float c = sigm(gf)*cin + sigm(gi)*tanhf(gg);
      float h = sigm(go)*tanhf(c);
      long o = ((long)(t+1)*BB + b0 + b)*DD + n0 + n;
      gS.H[o] = h;
      gS.C[o] = c;
    }
    if (t < TT-1) gbar_g(ctr, t, 32);
  }
}

// ---------------- prediction head -------------------------------------------
__global__ void head_kernel(const float* __restrict__ Wp, const float* __restrict__ bp,
                            float* __restrict__ out){
  int gw = (blockIdx.x*blockDim.x + threadIdx.x) >> 5;
  int lane = threadIdx.x & 31;
  if (gw >= BB*TT) return;
  int b = gw / TT, t = gw % TT;
  const float* h = gS.H + ((long)(t+1)*BB + b)*DD;
  float s = 0.f;
  for (int j = lane; j < DD; j += 32) s += h[j]*Wp[j];
  #pragma unroll
  for (int o = 16; o > 0; o >>= 1) s += __shfl_down_sync(0xffffffffu, s, o);
  if (lane == 0) out[b*TT + t] = sigm(s + bp[0]);
}

// ---------------- host orchestration ----------------------------------------
extern "C" void kernel_launch(void* const* d_in, const int* in_sizes, int n_in,
                              void* d_out, int out_size){
  (void)in_sizes; (void)n_in; (void)out_size;
  const int*   q     = (const int*)d_in[0];
  const int*   r     = (const int*)d_in[1];
  const float* Mk    = (const float*)d_in[2];
  const float* Mv0   = (const float*)d_in[3];
  const float* k_tab = (const float*)d_in[4];
  const float* x_tab = (const float*)d_in[5];
  const float* W_e   = (const float*)d_in[6];
  const float* b_e   = (const float*)d_in[7];
  const float* W_add = (const float*)d_in[8];
  const float* b_add = (const float*)d_in[9];
  const float* W_a   = (const float*)d_in[10];
  const float* b_a   = (const float*)d_in[11];
  const float* W_f   = (const float*)d_in[12];
  const float* b_f   = (const float*)d_in[13];
  const float* W_ih  = (const float*)d_in[14];
  const float* W_hh  = (const float*)d_in[15];
  const float* b_ih  = (const float*)d_in[16];
  const float* b_hh  = (const float*)d_in[17];
  const float* hx0   = (const float*)d_in[18];
  const float* cx0   = (const float*)d_in[19];
  const float* W_p   = (const float*)d_in[20];
  const float* b_p   = (const float*)d_in[21];
  float* out = (float*)d_out;

  Scratch* S = nullptr;
  cudaGetSymbolAddress((void**)&S, gS);

  cudaFuncSetAttribute(memrec_kernel, cudaFuncAttributeMaxDynamicSharedMemorySize, MEMREC_SMEM);
  cudaFuncSetAttribute(lstm_kernel,   cudaFuncAttributeMaxDynamicSharedMemorySize, LSTM_SMEM);

  const int ROWS = TT*BB; // 6144

  // 1: fused setup (inits + barrier reset + bias_ea + addressing)
  combo_kernel<<<NB_A + 128 + NC, 256>>>(q, r, hx0, cx0, b_ih, b_hh, W_a,
                                         W_e, W_add, b_a, b_e, b_add, Mk, k_tab);
  // 2: Aea/Bea in one launch                 (2 x 1024 x 512)
  sgemm2_dual_k<<<dim3(8,8), 256>>>(S->Sw, S->WaT, S->Wa2T, S->Aea, S->Bea);
  // 3: eaproj_t + kproj_t fused              (320 blocks)
  proj_fused_k<<<320, 256>>>(k_tab, x_tab, W_f, b_f);
  // 4: persistent memory recurrence (SMEM weights)  [profiled slot]
  memrec_kernel<<<128, 512, MEMREC_SMEM>>>(Mv0, W_f);
  // 5: hop-source search
  src_kernel<<<BB, 64>>>();
  // 6: xproj = f @ W_ih^T + (b_ih + b_hh)    (6144 x 2048)
  sgemm2_k<true><<<dim3(48,16), 256>>>(S->f, ROWS, W_ih, DD, S->bihh, S->xproj, 4*DD);
  // 7: persistent hop-LSTM (register-tiled)
  lstm_kernel<<<128, 256, LSTM_SMEM>>>(W_hh);
  // 8: head
  head_kernel<<<(BB*TT*32 + 255)/256, 256>>>(W_p, b_p, out);
}